// round 2
// baseline (speedup 1.0000x reference)
#include <cuda_runtime.h>

#define HH 200
#define WW 304
#define CC 256
#define NOUT 7
#define NSAMP 14          // NOUT * RATIO
#define NCORN 28          // 2 * NSAMP
#define TILE_PITCH 32     // padded row pitch (floats)
#define WARPS 8
#define CH_PER_BLOCK 64   // CC / CSPLIT
#define CSPLIT 4

__global__ __launch_bounds__(256)
void roi_align_kernel(const float* __restrict__ feat,
                      const float* __restrict__ boxes,
                      float* __restrict__ out)
{
    __shared__ int   s_cy[NCORN];
    __shared__ int   s_cx[NCORN];
    __shared__ float s_fy[NSAMP];
    __shared__ float s_fx[NSAMP];
    __shared__ int   s_vy[NSAMP];
    __shared__ int   s_vx[NSAMP];
    __shared__ __align__(16) float tile[WARPS][NCORN * TILE_PITCH];

    const int r   = blockIdx.x;
    const int tid = threadIdx.x;

    // ---- per-ROI bilinear metadata (threads 0..27) ----
    if (tid < 2 * NSAMP) {
        const int axis = tid / NSAMP;     // 0 = y, 1 = x
        const int i    = tid % NSAMP;
        const float b0 = boxes[r * 4 + (axis ? 0 : 1)] * 0.25f;  // x1 / y1
        const float b1 = boxes[r * 4 + (axis ? 2 : 3)] * 0.25f;  // x2 / y2
        const float len = fmaxf(b1 - b0, 1.0f);
        const float t   = b0 + (i + 0.5f) * 0.5f * (len / 7.0f);
        const int size  = axis ? WW : HH;
        const int valid = (t > -1.0f) && (t < (float)size);
        const float tc  = t < 0.0f ? 0.0f : t;
        const float low = floorf(tc);
        int lo, hi; float frac;
        if (low >= (float)(size - 1)) {
            lo = size - 1; hi = size - 1; frac = 0.0f;
        } else {
            lo = (int)low; hi = lo + 1; frac = tc - low;
        }
        if (axis) {
            s_cx[2 * i] = lo; s_cx[2 * i + 1] = hi; s_fx[i] = frac; s_vx[i] = valid;
        } else {
            s_cy[2 * i] = lo; s_cy[2 * i + 1] = hi; s_fy[i] = frac; s_vy[i] = valid;
        }
    }
    __syncthreads();

    const int warp = tid >> 5;
    const int lane = tid & 31;
    const int img  = r >> 9;                       // r / 512
    const float* fb = feat + (size_t)img * CC * HH * WW;
    float* tw = tile[warp];
    const int c0 = blockIdx.y * CH_PER_BLOCK;

    // each of the 28 "load lanes" owns one x-corner column; hoist the per-row
    // byte offsets (row*WW + mycx) into a per-lane base so the channel loop's
    // gather is pure pointer adds.
    const int mycx = (lane < NCORN) ? s_cx[lane] : 0;
    int rowoff[NCORN];
    #pragma unroll
    for (int a = 0; a < NCORN; a++) rowoff[a] = s_cy[a] * WW + mycx;

    for (int c = c0 + warp; c < c0 + CH_PER_BLOCK; c += WARPS) {
        const float* fc = fb + (size_t)c * (HH * WW);

        // ---- gather 28x28 corner grid, one warp-load per feature row ----
        if (lane < NCORN) {
            #pragma unroll
            for (int a = 0; a < NCORN; a++) {
                tw[a * TILE_PITCH + lane] = __ldg(fc + rowoff[a]);
            }
        }
        __syncwarp();

        // ---- compute 49 bins; each bin reads a disjoint 4x4 patch ----
        float* ob = out + ((size_t)r * CC + c) * (NOUT * NOUT);
        #pragma unroll
        for (int bb = 0; bb < 2; bb++) {
            const int bin = lane + bb * 32;
            if (bin < NOUT * NOUT) {
                const int py = bin / NOUT;
                const int px = bin - py * NOUT;
                float acc = 0.0f;
                #pragma unroll
                for (int ry = 0; ry < 2; ry++) {
                    const int sy  = 2 * py + ry;
                    const float fy = s_fy[sy];
                    const float hy = 1.0f - fy;
                    const int vy   = s_vy[sy];
                    // corner rows for this sample: 2*sy and 2*sy+1
                    const float4 rA = *(const float4*)(tw + (4 * py + 2 * ry) * TILE_PITCH + 4 * px);
                    const float4 rB = *(const float4*)(tw + (4 * py + 2 * ry + 1) * TILE_PITCH + 4 * px);
                    {   // rx = 0  -> corner cols 4*px, 4*px+1
                        const int sx = 2 * px;
                        const float fx = s_fx[sx];
                        const float v = hy * ((1.0f - fx) * rA.x + fx * rA.y)
                                      + fy * ((1.0f - fx) * rB.x + fx * rB.y);
                        if (vy && s_vx[sx]) acc += v;
                    }
                    {   // rx = 1  -> corner cols 4*px+2, 4*px+3
                        const int sx = 2 * px + 1;
                        const float fx = s_fx[sx];
                        const float v = hy * ((1.0f - fx) * rA.z + fx * rA.w)
                                      + fy * ((1.0f - fx) * rB.z + fx * rB.w);
                        if (vy && s_vx[sx]) acc += v;
                    }
                }
                ob[bin] = acc * 0.25f;   // mean over the fixed 2x2 sample group
            }
        }
        __syncwarp();
    }
}

extern "C" void kernel_launch(void* const* d_in, const int* in_sizes, int n_in,
                              void* d_out, int out_size)
{
    const float* feat  = (const float*)d_in[0];   // (2,256,200,304) f32
    const float* boxes = (const float*)d_in[1];   // (2,512,4) f32
    float* out = (float*)d_out;                   // (1024,256,7,7) f32

    dim3 grid(1024, CSPLIT);
    dim3 block(256);
    roi_align_kernel<<<grid, block>>>(feat, boxes, out);
}